// round 7
// baseline (speedup 1.0000x reference)
#include <cuda_runtime.h>

// ---------------------------------------------------------------------------
// KMeanReservoir: nearest-centroid assignment.
//   sim[n,k] = 2*x[n].c[k] - |x[n]|^2 - |c[k]|^2
//   out[0:N)   = max_k sim[n,k]           (float32)
//   out[N:2N)  = argmax_k sim[n,k]        (as float32)
//
// Shapes: x [131072, 256] f32, centroids [1024, 256] f32.
// Strategy: implicit GEMM with running max/argmax; fp32 via packed
// fma.rn.f32x2 (FFMA2) for 2x the scalar-FFMA rate on sm_103a.
// ---------------------------------------------------------------------------

typedef unsigned long long u64;

__device__ __forceinline__ u64 pack2(float lo, float hi) {
    u64 r;
    asm("mov.b64 %0, {%1, %2};" : "=l"(r) : "f"(lo), "f"(hi));
    return r;
}
__device__ __forceinline__ u64 ffma2(u64 a, u64 b, u64 c) {
    u64 d;
    asm("fma.rn.f32x2 %0, %1, %2, %3;" : "=l"(d) : "l"(a), "l"(b), "l"(c));
    return d;
}
__device__ __forceinline__ void unpack2(u64 v, float& lo, float& hi) {
    asm("mov.b64 {%0, %1}, %2;" : "=f"(lo), "=f"(hi) : "l"(v));
}

// Scratch (allocation-free: __device__ globals)
__device__ float g_cnorm[1024];
__device__ float g_xnorm[131072];

// ---------------------------------------------------------------------------
// Row-norm kernels: one warp per 256-float row.
// ---------------------------------------------------------------------------
__global__ void xnorm_kernel(const float* __restrict__ src, int rows) {
    int warp = (blockIdx.x * blockDim.x + threadIdx.x) >> 5;
    int lane = threadIdx.x & 31;
    if (warp >= rows) return;
    const float4* r = (const float4*)(src + (size_t)warp * 256);
    float4 a = r[lane];
    float4 b = r[lane + 32];
    float s = a.x * a.x + a.y * a.y + a.z * a.z + a.w * a.w +
              b.x * b.x + b.y * b.y + b.z * b.z + b.w * b.w;
#pragma unroll
    for (int o = 16; o; o >>= 1) s += __shfl_xor_sync(0xffffffffu, s, o);
    if (lane == 0) g_xnorm[warp] = s;
}

__global__ void cnorm_kernel(const float* __restrict__ src, int rows) {
    int warp = (blockIdx.x * blockDim.x + threadIdx.x) >> 5;
    int lane = threadIdx.x & 31;
    if (warp >= rows) return;
    const float4* r = (const float4*)(src + (size_t)warp * 256);
    float4 a = r[lane];
    float4 b = r[lane + 32];
    float s = a.x * a.x + a.y * a.y + a.z * a.z + a.w * a.w +
              b.x * b.x + b.y * b.y + b.z * b.z + b.w * b.w;
#pragma unroll
    for (int o = 16; o; o >>= 1) s += __shfl_xor_sync(0xffffffffu, s, o);
    if (lane == 0) g_cnorm[warp] = s;
}

// ---------------------------------------------------------------------------
// Main kernel.
//   Block: 256 threads (tx = tid&15, ty = tid>>4), BM=128 rows, BN=128 cents.
//   Per thread: TM=8 rows (ty*8..+7), TN=8 cols STRIDED (tx + 16*i).
//   D chunked by 16, double-buffered smem, d-major tiles xs[d][m], cs[d][n].
//   Accumulators: row-paired f32x2 (4 pairs x 8 cols = 32 u64).
// ---------------------------------------------------------------------------
__global__ __launch_bounds__(256) void assign_kernel(
    const float* __restrict__ x, const float* __restrict__ c,
    float* __restrict__ out, int Ntot) {
    __shared__ __align__(16) float xs[2][16 * 128];
    __shared__ __align__(16) float cs[2][16 * 128];

    const int tid = threadIdx.x;
    const int tx = tid & 15;
    const int ty = tid >> 4;
    const int rowBase = blockIdx.x * 128;

    // Staging-load mapping: thread covers float4 indices 2*tid, 2*tid+1 over
    // (m in 0..127) x (u in 0..3), i.e. 2048 floats = one 16x128 chunk.
    const int i0 = tid * 2, i1 = tid * 2 + 1;
    const int m0 = i0 >> 2, u0 = i0 & 3;
    const int m1 = i1 >> 2, u1 = i1 & 3;

    const float* xp0 = x + (size_t)(rowBase + m0) * 256 + u0 * 4;
    const float* xp1 = x + (size_t)(rowBase + m1) * 256 + u1 * 4;

    u64 acc[4][8];
    float bestv[8];
    int besti[8];
#pragma unroll
    for (int p = 0; p < 8; p++) { bestv[p] = -3.4e38f; besti[p] = 0; }

    float4 X0, X1, C0, C1;
    int buf = 0;

    for (int kt = 0; kt < 8; ++kt) {
        const int cBase = kt * 128;
        const float* cp0 = c + (size_t)(cBase + m0) * 256 + u0 * 4;
        const float* cp1 = c + (size_t)(cBase + m1) * 256 + u1 * 4;

#pragma unroll
        for (int p = 0; p < 4; p++)
#pragma unroll
            for (int i = 0; i < 8; i++) acc[p][i] = 0ull;

        float cn[8];
#pragma unroll
        for (int i = 0; i < 8; i++) cn[i] = g_cnorm[cBase + tx + 16 * i];

        // ---- load chunk dc = 0 ----
        X0 = *(const float4*)(xp0);
        X1 = *(const float4*)(xp1);
        C0 = *(const float4*)(cp0);
        C1 = *(const float4*)(cp1);
        {
            float* xd = xs[buf];
            xd[(u0 * 4 + 0) * 128 + m0] = X0.x; xd[(u0 * 4 + 1) * 128 + m0] = X0.y;
            xd[(u0 * 4 + 2) * 128 + m0] = X0.z; xd[(u0 * 4 + 3) * 128 + m0] = X0.w;
            xd[(u1 * 4 + 0) * 128 + m1] = X1.x; xd[(u1 * 4 + 1) * 128 + m1] = X1.y;
            xd[(u1 * 4 + 2) * 128 + m1] = X1.z; xd[(u1 * 4 + 3) * 128 + m1] = X1.w;
            float* cd = cs[buf];
            cd[(u0 * 4 + 0) * 128 + m0] = C0.x; cd[(u0 * 4 + 1) * 128 + m0] = C0.y;
            cd[(u0 * 4 + 2) * 128 + m0] = C0.z; cd[(u0 * 4 + 3) * 128 + m0] = C0.w;
            cd[(u1 * 4 + 0) * 128 + m1] = C1.x; cd[(u1 * 4 + 1) * 128 + m1] = C1.y;
            cd[(u1 * 4 + 2) * 128 + m1] = C1.z; cd[(u1 * 4 + 3) * 128 + m1] = C1.w;
        }
        __syncthreads();

        for (int dc = 0; dc < 16; ++dc) {
            // ---- issue next chunk's global loads (latency hidden by compute)
            if (dc < 15) {
                const int dcb = (dc + 1) * 16;
                X0 = *(const float4*)(xp0 + dcb);
                X1 = *(const float4*)(xp1 + dcb);
                C0 = *(const float4*)(cp0 + dcb);
                C1 = *(const float4*)(cp1 + dcb);
            }

            // ---- compute current chunk ----
            const float* xbuf = xs[buf];
            const float* cbuf = cs[buf];
#pragma unroll
            for (int kk = 0; kk < 16; ++kk) {
                const float* xrow = xbuf + kk * 128 + ty * 8;
                // A: two 16B loads = 4 row-pairs (broadcast, conflict-free)
                ulonglong2 A0 = *(const ulonglong2*)(xrow);
                ulonglong2 A1 = *(const ulonglong2*)(xrow + 4);
                // B: 8 strided scalar loads (conflict-free: banks = tx+16i)
                const float* crow = cbuf + kk * 128 + tx;
                u64 bd[8];
#pragma unroll
                for (int i = 0; i < 8; i++) {
                    float b = crow[16 * i];
                    bd[i] = pack2(b, b);
                }
                u64 ap0 = A0.x, ap1 = A0.y, ap2 = A1.x, ap3 = A1.y;
#pragma unroll
                for (int i = 0; i < 8; i++) {
                    acc[0][i] = ffma2(ap0, bd[i], acc[0][i]);
                    acc[1][i] = ffma2(ap1, bd[i], acc[1][i]);
                    acc[2][i] = ffma2(ap2, bd[i], acc[2][i]);
                    acc[3][i] = ffma2(ap3, bd[i], acc[3][i]);
                }
            }

            // ---- store staged next chunk into the other buffer ----
            if (dc < 15) {
                int nb = buf ^ 1;
                float* xd = xs[nb];
                xd[(u0 * 4 + 0) * 128 + m0] = X0.x; xd[(u0 * 4 + 1) * 128 + m0] = X0.y;
                xd[(u0 * 4 + 2) * 128 + m0] = X0.z; xd[(u0 * 4 + 3) * 128 + m0] = X0.w;
                xd[(u1 * 4 + 0) * 128 + m1] = X1.x; xd[(u1 * 4 + 1) * 128 + m1] = X1.y;
                xd[(u1 * 4 + 2) * 128 + m1] = X1.z; xd[(u1 * 4 + 3) * 128 + m1] = X1.w;
                float* cd = cs[nb];
                cd[(u0 * 4 + 0) * 128 + m0] = C0.x; cd[(u0 * 4 + 1) * 128 + m0] = C0.y;
                cd[(u0 * 4 + 2) * 128 + m0] = C0.z; cd[(u0 * 4 + 3) * 128 + m0] = C0.w;
                cd[(u1 * 4 + 0) * 128 + m1] = C1.x; cd[(u1 * 4 + 1) * 128 + m1] = C1.y;
                cd[(u1 * 4 + 2) * 128 + m1] = C1.z; cd[(u1 * 4 + 3) * 128 + m1] = C1.w;
            }
            __syncthreads();
            buf ^= 1;
        }

        // ---- K-tile epilogue: sim = 2*acc - |c|^2, update running argmax ----
#pragma unroll
        for (int p = 0; p < 4; p++) {
#pragma unroll
            for (int i = 0; i < 8; i++) {
                float lo, hi;
                unpack2(acc[p][i], lo, hi);
                int n = cBase + tx + 16 * i;
                float v0 = 2.0f * lo - cn[i];
                float v1 = 2.0f * hi - cn[i];
                if (v0 > bestv[2 * p])     { bestv[2 * p] = v0;     besti[2 * p] = n; }
                if (v1 > bestv[2 * p + 1]) { bestv[2 * p + 1] = v1; besti[2 * p + 1] = n; }
            }
        }
    }

    // ---- cross-thread (tx) reduction via reused smem ----
    __syncthreads();
    float* redv = &xs[0][0];    // 2048 floats needed, 4096 available
    int* redi = (int*)&cs[0][0];
#pragma unroll
    for (int p = 0; p < 8; p++) {
        int row = ty * 8 + p;
        redv[row * 16 + tx] = bestv[p];
        redi[row * 16 + tx] = besti[p];
    }
    __syncthreads();
    if (tid < 128) {
        int row = tid;
        float bv = redv[row * 16];
        int bi = redi[row * 16];
#pragma unroll
        for (int j = 1; j < 16; j++) {
            float v = redv[row * 16 + j];
            int id = redi[row * 16 + j];
            if (v > bv || (v == bv && id < bi)) { bv = v; bi = id; }
        }
        int g = rowBase + row;
        out[g] = bv - g_xnorm[g];          // max_sim
        out[Ntot + g] = (float)bi;         // label as float
    }
}

// ---------------------------------------------------------------------------
extern "C" void kernel_launch(void* const* d_in, const int* in_sizes, int n_in,
                              void* d_out, int out_size) {
    const float* x = (const float*)d_in[0];
    const float* c = (const float*)d_in[1];
    float* out = (float*)d_out;

    const int D = 256;
    const int N = in_sizes[0] / D;   // 131072
    const int K = in_sizes[1] / D;   // 1024

    // Norms (one warp per row; 8 rows per 256-thread block)
    cnorm_kernel<<<(K + 7) / 8, 256>>>(c, K);
    xnorm_kernel<<<(N + 7) / 8, 256>>>(x, N);

    // Main assignment: BM=128 rows per block
    assign_kernel<<<N / 128, 256>>>(x, c, out, N);
}

// round 8
// speedup vs baseline: 1.0014x; 1.0014x over previous
#include <cuda_runtime.h>

// ---------------------------------------------------------------------------
// KMeanReservoir: nearest-centroid assignment.
//   sim[n,k] = 2*x[n].c[k] - |x[n]|^2 - |c[k]|^2
//   out[0:N)   = max_k sim[n,k]           (float32)
//   out[N:2N)  = argmax_k sim[n,k]        (as float32)
//
// Shapes: x [131072, 256] f32, centroids [1024, 256] f32.
// Strategy: implicit GEMM with running max/argmax; fp32 via packed
// fma.rn.f32x2 (FFMA2) for 2x the scalar-FFMA rate on sm_103a.
// ---------------------------------------------------------------------------

typedef unsigned long long u64;

__device__ __forceinline__ u64 pack2(float lo, float hi) {
    u64 r;
    asm("mov.b64 %0, {%1, %2};" : "=l"(r) : "f"(lo), "f"(hi));
    return r;
}
__device__ __forceinline__ u64 ffma2(u64 a, u64 b, u64 c) {
    u64 d;
    asm("fma.rn.f32x2 %0, %1, %2, %3;" : "=l"(d) : "l"(a), "l"(b), "l"(c));
    return d;
}
__device__ __forceinline__ void unpack2(u64 v, float& lo, float& hi) {
    asm("mov.b64 {%0, %1}, %2;" : "=f"(lo), "=f"(hi) : "l"(v));
}

// Scratch (allocation-free: __device__ globals)
__device__ float g_cnorm[1024];
__device__ float g_xnorm[131072];

// ---------------------------------------------------------------------------
// Row-norm kernels: one warp per 256-float row.
// ---------------------------------------------------------------------------
__global__ void xnorm_kernel(const float* __restrict__ src, int rows) {
    int warp = (blockIdx.x * blockDim.x + threadIdx.x) >> 5;
    int lane = threadIdx.x & 31;
    if (warp >= rows) return;
    const float4* r = (const float4*)(src + (size_t)warp * 256);
    float4 a = r[lane];
    float4 b = r[lane + 32];
    float s = a.x * a.x + a.y * a.y + a.z * a.z + a.w * a.w +
              b.x * b.x + b.y * b.y + b.z * b.z + b.w * b.w;
#pragma unroll
    for (int o = 16; o; o >>= 1) s += __shfl_xor_sync(0xffffffffu, s, o);
    if (lane == 0) g_xnorm[warp] = s;
}

__global__ void cnorm_kernel(const float* __restrict__ src, int rows) {
    int warp = (blockIdx.x * blockDim.x + threadIdx.x) >> 5;
    int lane = threadIdx.x & 31;
    if (warp >= rows) return;
    const float4* r = (const float4*)(src + (size_t)warp * 256);
    float4 a = r[lane];
    float4 b = r[lane + 32];
    float s = a.x * a.x + a.y * a.y + a.z * a.z + a.w * a.w +
              b.x * b.x + b.y * b.y + b.z * b.z + b.w * b.w;
#pragma unroll
    for (int o = 16; o; o >>= 1) s += __shfl_xor_sync(0xffffffffu, s, o);
    if (lane == 0) g_cnorm[warp] = s;
}

// ---------------------------------------------------------------------------
// Main kernel.
//   Block: 256 threads (tx = tid&15, ty = tid>>4), BM=128 rows, BN=128 cents.
//   Per thread: TM=8 rows (ty*8..+7), TN=8 cols STRIDED (tx + 16*i).
//   D chunked by 16, double-buffered smem, d-major tiles xs[d][m], cs[d][n].
//   Accumulators: row-paired f32x2 (4 pairs x 8 cols = 32 u64).
// ---------------------------------------------------------------------------
__global__ __launch_bounds__(256) void assign_kernel(
    const float* __restrict__ x, const float* __restrict__ c,
    float* __restrict__ out, int Ntot) {
    __shared__ __align__(16) float xs[2][16 * 128];
    __shared__ __align__(16) float cs[2][16 * 128];

    const int tid = threadIdx.x;
    const int tx = tid & 15;
    const int ty = tid >> 4;
    const int rowBase = blockIdx.x * 128;

    // Staging-load mapping: thread covers float4 indices 2*tid, 2*tid+1 over
    // (m in 0..127) x (u in 0..3), i.e. 2048 floats = one 16x128 chunk.
    const int i0 = tid * 2, i1 = tid * 2 + 1;
    const int m0 = i0 >> 2, u0 = i0 & 3;
    const int m1 = i1 >> 2, u1 = i1 & 3;

    const float* xp0 = x + (size_t)(rowBase + m0) * 256 + u0 * 4;
    const float* xp1 = x + (size_t)(rowBase + m1) * 256 + u1 * 4;

    u64 acc[4][8];
    float bestv[8];
    int besti[8];
#pragma unroll
    for (int p = 0; p < 8; p++) { bestv[p] = -3.4e38f; besti[p] = 0; }

    float4 X0, X1, C0, C1;
    int buf = 0;

    for (int kt = 0; kt < 8; ++kt) {
        const int cBase = kt * 128;
        const float* cp0 = c + (size_t)(cBase + m0) * 256 + u0 * 4;
        const float* cp1 = c + (size_t)(cBase + m1) * 256 + u1 * 4;

#pragma unroll
        for (int p = 0; p < 4; p++)
#pragma unroll
            for (int i = 0; i < 8; i++) acc[p][i] = 0ull;

        float cn[8];
#pragma unroll
        for (int i = 0; i < 8; i++) cn[i] = g_cnorm[cBase + tx + 16 * i];

        // ---- load chunk dc = 0 ----
        X0 = *(const float4*)(xp0);
        X1 = *(const float4*)(xp1);
        C0 = *(const float4*)(cp0);
        C1 = *(const float4*)(cp1);
        {
            float* xd = xs[buf];
            xd[(u0 * 4 + 0) * 128 + m0] = X0.x; xd[(u0 * 4 + 1) * 128 + m0] = X0.y;
            xd[(u0 * 4 + 2) * 128 + m0] = X0.z; xd[(u0 * 4 + 3) * 128 + m0] = X0.w;
            xd[(u1 * 4 + 0) * 128 + m1] = X1.x; xd[(u1 * 4 + 1) * 128 + m1] = X1.y;
            xd[(u1 * 4 + 2) * 128 + m1] = X1.z; xd[(u1 * 4 + 3) * 128 + m1] = X1.w;
            float* cd = cs[buf];
            cd[(u0 * 4 + 0) * 128 + m0] = C0.x; cd[(u0 * 4 + 1) * 128 + m0] = C0.y;
            cd[(u0 * 4 + 2) * 128 + m0] = C0.z; cd[(u0 * 4 + 3) * 128 + m0] = C0.w;
            cd[(u1 * 4 + 0) * 128 + m1] = C1.x; cd[(u1 * 4 + 1) * 128 + m1] = C1.y;
            cd[(u1 * 4 + 2) * 128 + m1] = C1.z; cd[(u1 * 4 + 3) * 128 + m1] = C1.w;
        }
        __syncthreads();

        for (int dc = 0; dc < 16; ++dc) {
            // ---- issue next chunk's global loads (latency hidden by compute)
            if (dc < 15) {
                const int dcb = (dc + 1) * 16;
                X0 = *(const float4*)(xp0 + dcb);
                X1 = *(const float4*)(xp1 + dcb);
                C0 = *(const float4*)(cp0 + dcb);
                C1 = *(const float4*)(cp1 + dcb);
            }

            // ---- compute current chunk ----
            const float* xbuf = xs[buf];
            const float* cbuf = cs[buf];
#pragma unroll
            for (int kk = 0; kk < 16; ++kk) {
                const float* xrow = xbuf + kk * 128 + ty * 8;
                // A: two 16B loads = 4 row-pairs (broadcast, conflict-free)
                ulonglong2 A0 = *(const ulonglong2*)(xrow);
                ulonglong2 A1 = *(const ulonglong2*)(xrow + 4);
                // B: 8 strided scalar loads (conflict-free: banks = tx+16i)
                const float* crow = cbuf + kk * 128 + tx;
                u64 bd[8];
#pragma unroll
                for (int i = 0; i < 8; i++) {
                    float b = crow[16 * i];
                    bd[i] = pack2(b, b);
                }
                u64 ap0 = A0.x, ap1 = A0.y, ap2 = A1.x, ap3 = A1.y;
#pragma unroll
                for (int i = 0; i < 8; i++) {
                    acc[0][i] = ffma2(ap0, bd[i], acc[0][i]);
                    acc[1][i] = ffma2(ap1, bd[i], acc[1][i]);
                    acc[2][i] = ffma2(ap2, bd[i], acc[2][i]);
                    acc[3][i] = ffma2(ap3, bd[i], acc[3][i]);
                }
            }

            // ---- store staged next chunk into the other buffer ----
            if (dc < 15) {
                int nb = buf ^ 1;
                float* xd = xs[nb];
                xd[(u0 * 4 + 0) * 128 + m0] = X0.x; xd[(u0 * 4 + 1) * 128 + m0] = X0.y;
                xd[(u0 * 4 + 2) * 128 + m0] = X0.z; xd[(u0 * 4 + 3) * 128 + m0] = X0.w;
                xd[(u1 * 4 + 0) * 128 + m1] = X1.x; xd[(u1 * 4 + 1) * 128 + m1] = X1.y;
                xd[(u1 * 4 + 2) * 128 + m1] = X1.z; xd[(u1 * 4 + 3) * 128 + m1] = X1.w;
                float* cd = cs[nb];
                cd[(u0 * 4 + 0) * 128 + m0] = C0.x; cd[(u0 * 4 + 1) * 128 + m0] = C0.y;
                cd[(u0 * 4 + 2) * 128 + m0] = C0.z; cd[(u0 * 4 + 3) * 128 + m0] = C0.w;
                cd[(u1 * 4 + 0) * 128 + m1] = C1.x; cd[(u1 * 4 + 1) * 128 + m1] = C1.y;
                cd[(u1 * 4 + 2) * 128 + m1] = C1.z; cd[(u1 * 4 + 3) * 128 + m1] = C1.w;
            }
            __syncthreads();
            buf ^= 1;
        }

        // ---- K-tile epilogue: sim = 2*acc - |c|^2, update running argmax ----
#pragma unroll
        for (int p = 0; p < 4; p++) {
#pragma unroll
            for (int i = 0; i < 8; i++) {
                float lo, hi;
                unpack2(acc[p][i], lo, hi);
                int n = cBase + tx + 16 * i;
                float v0 = 2.0f * lo - cn[i];
                float v1 = 2.0f * hi - cn[i];
                if (v0 > bestv[2 * p])     { bestv[2 * p] = v0;     besti[2 * p] = n; }
                if (v1 > bestv[2 * p + 1]) { bestv[2 * p + 1] = v1; besti[2 * p + 1] = n; }
            }
        }
    }

    // ---- cross-thread (tx) reduction via reused smem ----
    __syncthreads();
    float* redv = &xs[0][0];    // 2048 floats needed, 4096 available
    int* redi = (int*)&cs[0][0];
#pragma unroll
    for (int p = 0; p < 8; p++) {
        int row = ty * 8 + p;
        redv[row * 16 + tx] = bestv[p];
        redi[row * 16 + tx] = besti[p];
    }
    __syncthreads();
    if (tid < 128) {
        int row = tid;
        float bv = redv[row * 16];
        int bi = redi[row * 16];
#pragma unroll
        for (int j = 1; j < 16; j++) {
            float v = redv[row * 16 + j];
            int id = redi[row * 16 + j];
            if (v > bv || (v == bv && id < bi)) { bv = v; bi = id; }
        }
        int g = rowBase + row;
        out[g] = bv - g_xnorm[g];          // max_sim
        out[Ntot + g] = (float)bi;         // label as float
    }
}

// ---------------------------------------------------------------------------
extern "C" void kernel_launch(void* const* d_in, const int* in_sizes, int n_in,
                              void* d_out, int out_size) {
    const float* x = (const float*)d_in[0];
    const float* c = (const float*)d_in[1];
    float* out = (float*)d_out;

    const int D = 256;
    const int N = in_sizes[0] / D;   // 131072
    const int K = in_sizes[1] / D;   // 1024

    // Norms (one warp per row; 8 rows per 256-thread block)
    cnorm_kernel<<<(K + 7) / 8, 256>>>(c, K);
    xnorm_kernel<<<(N + 7) / 8, 256>>>(x, N);

    // Main assignment: BM=128 rows per block
    assign_kernel<<<N / 128, 256>>>(x, c, out, N);
}